// round 4
// baseline (speedup 1.0000x reference)
#include <cuda_runtime.h>
#include <math.h>

#define MAX_N     16
#define NBINS     4096
#define CAND_MAX  4096
#define BT_MAX    16384
#define H_THREADS 1024
#define H_BPB     37
#define C_THREADS 1024
#define C_BPB     37

__device__ unsigned int       g_hist[MAX_N * NBINS];
__device__ unsigned int       g_subhist[MAX_N * NBINS];
__device__ int                g_count[MAX_N];
__device__ int                g_btcount[MAX_N];
__device__ int                g_T[MAX_N];
__device__ int                g_S[MAX_N];
__device__ unsigned int       g_done1[MAX_N];
__device__ unsigned int       g_done2[MAX_N];
__device__ unsigned long long g_cand[MAX_N * CAND_MAX];
__device__ unsigned long long g_binT[MAX_N * BT_MAX];

__device__ __forceinline__ unsigned int mono_f32(float f) {
    unsigned int u = __float_as_uint(f);
    return (u & 0x80000000u) ? ~u : (u | 0x80000000u);
}
__device__ __forceinline__ float inv_mono(unsigned int m) {
    unsigned int u = (m & 0x80000000u) ? (m & 0x7FFFFFFFu) : ~m;
    return __uint_as_float(u);
}
__device__ __forceinline__ unsigned long long umax64(unsigned long long a, unsigned long long b) { return a > b ? a : b; }
__device__ __forceinline__ unsigned long long umin64(unsigned long long a, unsigned long long b) { return a < b ? a : b; }

// warp-aggregated shared-hist add
__device__ __forceinline__ void hist_add(unsigned int* sh, unsigned int bin) {
    unsigned int mm = __match_any_sync(__activemask(), bin);
    int leader = __ffs(mm) - 1;
    if ((int)(threadIdx.x & 31) == leader) atomicAdd(&sh[bin], (unsigned int)__popc(mm));
}

__device__ __forceinline__ void hist4(unsigned int* sh, float4 v) {
    hist_add(sh, mono_f32(v.x) >> 20);
    hist_add(sh, mono_f32(v.y) >> 20);
    hist_add(sh, mono_f32(v.z) >> 20);
    hist_add(sh, mono_f32(v.w) >> 20);
}

// ---------------------------------------------------------------------------
// Kernel 1: hist sweep (4-way staged loads) + per-batch finisher computes
// threshold bin T and S, zeroes state for this replay's pass-2 / next replay.
// grid (H_BPB, N), block 1024
// ---------------------------------------------------------------------------
__global__ void __launch_bounds__(H_THREADS, 2)
hist_thresh_kernel(const float* __restrict__ scores, int A, int k) {
    __shared__ unsigned int sh[NBINS];
    __shared__ unsigned int tmp[H_THREADS];
    __shared__ bool s_last;
    const int b = blockIdx.y;
    const int t = threadIdx.x;

    for (int i = t; i < NBINS; i += H_THREADS) sh[i] = 0;
    __syncthreads();

    const size_t base = (size_t)b * (size_t)A;
    const int stride = H_BPB * H_THREADS;
    if ((A & 3) == 0) {
        const float4* s4 = (const float4*)(scores + base);
        const int A4 = A >> 2;
        for (int i = blockIdx.x * H_THREADS + t; i < A4; i += 4 * stride) {
            // stage 4 independent loads for MLP
            int i1 = i + stride, i2 = i + 2 * stride, i3 = i + 3 * stride;
            float4 v0 = s4[i];
            float4 v1, v2, v3;
            if (i1 < A4) v1 = s4[i1];
            if (i2 < A4) v2 = s4[i2];
            if (i3 < A4) v3 = s4[i3];
            hist4(sh, v0);
            if (i1 < A4) hist4(sh, v1);
            if (i2 < A4) hist4(sh, v2);
            if (i3 < A4) hist4(sh, v3);
        }
    } else {
        for (int i = blockIdx.x * H_THREADS + t; i < A; i += stride)
            hist_add(sh, mono_f32(scores[base + i]) >> 20);
    }
    __syncthreads();
    for (int i = t; i < NBINS; i += H_THREADS) {
        unsigned int c = sh[i];
        if (c) atomicAdd(&g_hist[b * NBINS + i], c);
    }
    __threadfence();
    __syncthreads();
    if (t == 0) s_last = (atomicAdd(&g_done1[b], 1u) == (unsigned)gridDim.x - 1u);
    __syncthreads();
    if (!s_last) return;

    // ---- finisher: threshold from full histogram ----
    if (t == 0) g_done1[b] = 0;
    for (int i = t; i < NBINS; i += H_THREADS) sh[i] = g_hist[b * NBINS + i];
    __syncthreads();

    unsigned int seg = sh[t * 4] + sh[t * 4 + 1] + sh[t * 4 + 2] + sh[t * 4 + 3];
    tmp[t] = seg;
    __syncthreads();
    for (int d = 1; d < H_THREADS; d <<= 1) {
        unsigned int v = (t + d < H_THREADS) ? tmp[t + d] : 0u;
        __syncthreads();
        tmp[t] += v;
        __syncthreads();
    }
    unsigned int sufMine = tmp[t];
    unsigned int sufNext = (t + 1 < H_THREADS) ? tmp[t + 1] : 0u;
    if (sufMine >= (unsigned)k && sufNext < (unsigned)k) {
        unsigned int acc = sufNext;
        for (int j = 3; j >= 0; j--) {
            unsigned int c = sh[t * 4 + j];
            if (acc + c >= (unsigned)k) { g_T[b] = t * 4 + j; g_S[b] = (int)acc; break; }
            acc += c;
        }
    }
    for (int i = t; i < NBINS; i += H_THREADS) {
        g_hist[b * NBINS + i] = 0;
        g_subhist[b * NBINS + i] = 0;
    }
    if (t == 0) { g_count[b] = 0; g_btcount[b] = 0; }
}

// ---------------------------------------------------------------------------
__device__ __forceinline__ void decode_write(unsigned long long key,
                                             const float* __restrict__ anchors,
                                             const float* __restrict__ breg,
                                             float* __restrict__ out,
                                             size_t base, int b, int rank, int k) {
    const float CLIP = 4.135166556742356f;  // log(1000/16)
    unsigned int idx = 0xFFFFFFFFu - (unsigned int)(key & 0xFFFFFFFFull);
    float sc = inv_mono((unsigned int)(key >> 32));
    size_t g4 = (base + (size_t)idx) * 4;

    float4 box = *(const float4*)(anchors + g4);
    float4 rc  = *(const float4*)(breg + g4);

    float w  = box.z - box.x + 1.0f;
    float h  = box.w - box.y + 1.0f;
    float cx = box.x + 0.5f * w;
    float cy = box.y + 0.5f * h;

    float dw = fminf(rc.z, CLIP);
    float dh = fminf(rc.w, CLIP);

    float pcx = rc.x * w + cx;
    float pcy = rc.y * h + cy;
    float pw  = expf(dw) * w;
    float ph  = expf(dh) * h;

    float* o = out + ((size_t)b * k + rank) * 5;
    o[0] = pcx - 0.5f * pw;
    o[1] = pcy - 0.5f * ph;
    o[2] = pcx + 0.5f * pw - 1.0f;
    o[3] = pcy + 0.5f * ph - 1.0f;
    o[4] = sc;
}

__device__ __forceinline__ void compact_one(unsigned int m, unsigned int off,
                                            int b, int T) {
    int bin = (int)(m >> 20);
    if (bin < T) return;
    unsigned long long key = ((unsigned long long)m << 32) |
                             (unsigned long long)(0xFFFFFFFFu - off);
    if (bin > T) {
        int p = atomicAdd(&g_count[b], 1);
        if (p < CAND_MAX) g_cand[b * CAND_MAX + p] = key;
    } else {
        atomicAdd(&g_subhist[b * NBINS + ((m >> 8) & 0xFFFu)], 1u);
        int p = atomicAdd(&g_btcount[b], 1);
        if (p < BT_MAX) g_binT[b * BT_MAX + p] = key;
    }
}

__device__ __forceinline__ void compact4(float4 v, unsigned int o, int b, int T) {
    compact_one(mono_f32(v.x), o + 0u, b, T);
    compact_one(mono_f32(v.y), o + 1u, b, T);
    compact_one(mono_f32(v.z), o + 2u, b, T);
    compact_one(mono_f32(v.w), o + 3u, b, T);
}

// ---------------------------------------------------------------------------
// Kernel 2: compact sweep (4-way staged) + per-batch finisher: refine T2,
// assemble ~k candidates, register-hybrid bitonic sort, decode, write.
// grid (C_BPB, N), block 1024, dynsmem 4096*8
// ---------------------------------------------------------------------------
__global__ void __launch_bounds__(C_THREADS, 2)
compact_sort_kernel(const float* __restrict__ scores,
                    const float* __restrict__ anchors,
                    const float* __restrict__ breg,
                    float* __restrict__ out,
                    int A, int k) {
    extern __shared__ unsigned long long s[];
    __shared__ unsigned int tmp[C_THREADS];
    __shared__ int sT2, sCnt;
    __shared__ bool s_last;
    const int b = blockIdx.y;
    const int t = threadIdx.x;
    const int T = g_T[b];
    const size_t base = (size_t)b * (size_t)A;
    const int stride = C_BPB * C_THREADS;

    if ((A & 3) == 0) {
        const float4* s4 = (const float4*)(scores + base);
        const int A4 = A >> 2;
        for (int i = blockIdx.x * C_THREADS + t; i < A4; i += 4 * stride) {
            int i1 = i + stride, i2 = i + 2 * stride, i3 = i + 3 * stride;
            float4 v0 = s4[i];
            float4 v1, v2, v3;
            if (i1 < A4) v1 = s4[i1];
            if (i2 < A4) v2 = s4[i2];
            if (i3 < A4) v3 = s4[i3];
            compact4(v0, (unsigned)(i << 2), b, T);
            if (i1 < A4) compact4(v1, (unsigned)(i1 << 2), b, T);
            if (i2 < A4) compact4(v2, (unsigned)(i2 << 2), b, T);
            if (i3 < A4) compact4(v3, (unsigned)(i3 << 2), b, T);
        }
    } else {
        for (int i = blockIdx.x * C_THREADS + t; i < A; i += stride)
            compact_one(mono_f32(scores[base + i]), (unsigned)i, b, T);
    }
    __threadfence();
    __syncthreads();
    if (t == 0) s_last = (atomicAdd(&g_done2[b], 1u) == (unsigned)gridDim.x - 1u);
    __syncthreads();
    if (!s_last) return;
    if (t == 0) g_done2[b] = 0;

    // ---- Phase A: refined sub-threshold T2 within bin T ----
    unsigned int* shist = (unsigned int*)s;
    for (int i = t; i < NBINS; i += C_THREADS) shist[i] = g_subhist[b * NBINS + i];
    const int S  = g_S[b];
    const int k2 = k - S;
    __syncthreads();

    unsigned int seg = shist[t * 4] + shist[t * 4 + 1] + shist[t * 4 + 2] + shist[t * 4 + 3];
    tmp[t] = seg;
    __syncthreads();
    for (int d = 1; d < C_THREADS; d <<= 1) {
        unsigned int v = (t + d < C_THREADS) ? tmp[t + d] : 0u;
        __syncthreads();
        tmp[t] += v;
        __syncthreads();
    }
    unsigned int sufMine = tmp[t];
    unsigned int sufNext = (t + 1 < C_THREADS) ? tmp[t + 1] : 0u;
    if (sufMine >= (unsigned)k2 && sufNext < (unsigned)k2) {
        unsigned int acc = sufNext;
        for (int j = 3; j >= 0; j--) {
            unsigned int c = shist[t * 4 + j];
            if (acc + c >= (unsigned)k2) { sT2 = t * 4 + j; break; }
            acc += c;
        }
    }
    __syncthreads();
    const int T2 = sT2;
    const int C  = min(g_count[b], CAND_MAX);
    const int BT = min(g_btcount[b], BT_MAX);
    if (t == 0) sCnt = C;
    __syncthreads();

    // ---- Phase B: assemble candidate list ----
    for (int i = t; i < C; i += C_THREADS) s[i] = g_cand[b * CAND_MAX + i];
    for (int i = t; i < BT; i += C_THREADS) {
        unsigned long long key = g_binT[b * BT_MAX + i];
        if ((int)((key >> 40) & 0xFFFull) >= T2) {
            int p = atomicAdd(&sCnt, 1);
            if (p < 4096) s[p] = key;
        }
    }
    __syncthreads();
    int Ct = sCnt; if (Ct > 4096) Ct = 4096;

    if (Ct <= 2048) {
        // ---- register-resident hybrid bitonic, P = 2048 ----
        unsigned long long r0 = (t        < Ct) ? s[t]        : 0ull;
        unsigned long long r1 = (t + 1024 < Ct) ? s[t + 1024] : 0ull;

        for (unsigned int kk = 2; kk <= 2048u; kk <<= 1) {
            for (unsigned int jj = kk >> 1; jj >= 32u; jj >>= 1) {
                if (jj == 1024u) {
                    bool d = ((t & kk) == 0);
                    unsigned long long mx = umax64(r0, r1), mn = umin64(r0, r1);
                    r0 = d ? mx : mn; r1 = d ? mn : mx;
                } else {
                    s[t] = r0; s[t + 1024] = r1;
                    __syncthreads();
                    unsigned long long p0 = s[t ^ jj];
                    unsigned long long p1 = s[(t + 1024) ^ jj];
                    bool l  = ((t & jj) == 0);
                    bool d0 = ((t & kk) == 0);
                    bool d1 = (((t + 1024) & kk) == 0);
                    r0 = (d0 == l) ? umax64(r0, p0) : umin64(r0, p0);
                    r1 = (d1 == l) ? umax64(r1, p1) : umin64(r1, p1);
                    __syncthreads();
                }
            }
            unsigned int jtop = (kk >> 1 < 16u) ? (kk >> 1) : 16u;
            for (unsigned int jj = jtop; jj >= 1u; jj >>= 1) {
                unsigned long long p0 = __shfl_xor_sync(0xFFFFFFFFu, r0, jj);
                unsigned long long p1 = __shfl_xor_sync(0xFFFFFFFFu, r1, jj);
                bool l  = ((t & jj) == 0);
                bool d0 = ((t & kk) == 0);
                bool d1 = (((t + 1024) & kk) == 0);
                r0 = (d0 == l) ? umax64(r0, p0) : umin64(r0, p0);
                r1 = (d1 == l) ? umax64(r1, p1) : umin64(r1, p1);
            }
        }
        decode_write(r0, anchors, breg, out, base, b, t, k);
        if (t + 1024 < k) decode_write(r1, anchors, breg, out, base, b, t + 1024, k);
    } else {
        int P = 2048;
        while (P < Ct) P <<= 1;
        for (int i = t; i < P; i += C_THREADS)
            if (i >= Ct) s[i] = 0ull;
        __syncthreads();
        for (unsigned int kk = 2; kk <= (unsigned int)P; kk <<= 1) {
            for (unsigned int jj = kk >> 1; jj > 0; jj >>= 1) {
                for (unsigned int i = t; i < (unsigned int)P; i += C_THREADS) {
                    unsigned int ixj = i ^ jj;
                    if (ixj > i) {
                        unsigned long long a = s[i], c2 = s[ixj];
                        bool desc = ((i & kk) == 0);
                        if (desc ? (a < c2) : (a > c2)) { s[i] = c2; s[ixj] = a; }
                    }
                }
                __syncthreads();
            }
        }
        for (int i = t; i < k; i += C_THREADS)
            decode_write(s[i], anchors, breg, out, base, b, i, k);
    }
}

// ---------------------------------------------------------------------------
extern "C" void kernel_launch(void* const* d_in, const int* in_sizes, int n_in,
                              void* d_out, int out_size) {
    const float* anchors    = (const float*)d_in[0];
    const float* objectness = (const float*)d_in[1];
    const float* breg       = (const float*)d_in[2];
    float* out = (float*)d_out;

    const int NA = in_sizes[1];
    const int k  = 2000;
    const int N  = out_size / (k * 5);
    const int A  = NA / N;

    dim3 g1(H_BPB, N);
    hist_thresh_kernel<<<g1, H_THREADS>>>(objectness, A, k);

    dim3 g2(C_BPB, N);
    compact_sort_kernel<<<g2, C_THREADS, 4096 * sizeof(unsigned long long)>>>(
        objectness, anchors, breg, out, A, k);
}

// round 5
// speedup vs baseline: 1.6656x; 1.6656x over previous
#include <cuda_runtime.h>
#include <math.h>

#define MAX_N    16
#define NBINS    4096
#define CAND_MAX 4096
#define BT_MAX   16384
#define HT       1024
#define BPB      18
#define RB       32      // rank blocks per batch

__device__ unsigned int       g_hist[MAX_N * NBINS];
__device__ unsigned int       g_subhist[MAX_N * NBINS];
__device__ int                g_count[MAX_N];
__device__ int                g_btcount[MAX_N];
__device__ int                g_T[MAX_N];
__device__ int                g_S[MAX_N];
__device__ int                g_total[MAX_N];
__device__ int                g_rank[MAX_N * CAND_MAX];
__device__ unsigned long long g_cand[MAX_N * CAND_MAX];
__device__ unsigned long long g_binT[MAX_N * BT_MAX];

__device__ __forceinline__ unsigned int mono_f32(float f) {
    unsigned int u = __float_as_uint(f);
    return (u & 0x80000000u) ? ~u : (u | 0x80000000u);
}
__device__ __forceinline__ float inv_mono(unsigned int m) {
    unsigned int u = (m & 0x80000000u) ? (m & 0x7FFFFFFFu) : ~m;
    return __uint_as_float(u);
}

// ---------------------------------------------------------------------------
// Pass 1: per-batch 12-bit histogram (plain shared atomics, float4 sweep)
// grid (BPB, N) x HT
// ---------------------------------------------------------------------------
__global__ void hist_kernel(const float* __restrict__ scores, int A) {
    __shared__ unsigned int sh[NBINS];
    const int b = blockIdx.y;
    for (int i = threadIdx.x; i < NBINS; i += HT) sh[i] = 0;
    __syncthreads();

    const size_t base = (size_t)b * (size_t)A;
    if ((A & 3) == 0) {
        const float4* s4 = (const float4*)(scores + base);
        const int A4 = A >> 2;
        for (int i = blockIdx.x * HT + threadIdx.x; i < A4; i += BPB * HT) {
            float4 v = s4[i];
            atomicAdd(&sh[mono_f32(v.x) >> 20], 1u);
            atomicAdd(&sh[mono_f32(v.y) >> 20], 1u);
            atomicAdd(&sh[mono_f32(v.z) >> 20], 1u);
            atomicAdd(&sh[mono_f32(v.w) >> 20], 1u);
        }
    } else {
        for (int i = blockIdx.x * HT + threadIdx.x; i < A; i += BPB * HT)
            atomicAdd(&sh[mono_f32(scores[base + i]) >> 20], 1u);
    }
    __syncthreads();
    for (int i = threadIdx.x; i < NBINS; i += HT) {
        unsigned int c = sh[i];
        if (c) atomicAdd(&g_hist[b * NBINS + i], c);
    }
}

// ---------------------------------------------------------------------------
// Pass 2: threshold bin T, S = count strictly above T. Zeroes per-replay state.
// grid N x 256
// ---------------------------------------------------------------------------
__global__ void thresh_kernel(int k) {
    const int b = blockIdx.x;
    const int t = threadIdx.x;   // 256 threads, 16 bins each
    __shared__ unsigned int h[NBINS];
    __shared__ unsigned int tmp[256];

    for (int i = t; i < NBINS; i += 256) {
        h[i] = g_hist[b * NBINS + i];
        g_subhist[b * NBINS + i] = 0;
    }
    for (int i = t; i < CAND_MAX; i += 256) g_rank[b * CAND_MAX + i] = 0;
    if (t == 0) { g_count[b] = 0; g_btcount[b] = 0; }
    __syncthreads();

    unsigned int s = 0;
#pragma unroll
    for (int j = 0; j < 16; j++) s += h[t * 16 + j];
    tmp[t] = s;
    __syncthreads();
    for (int d = 1; d < 256; d <<= 1) {
        unsigned int v = (t + d < 256) ? tmp[t + d] : 0u;
        __syncthreads();
        tmp[t] += v;
        __syncthreads();
    }
    unsigned int sufMine = tmp[t];
    unsigned int sufNext = (t + 1 < 256) ? tmp[t + 1] : 0u;
    if (sufMine >= (unsigned)k && sufNext < (unsigned)k) {
        unsigned int acc = sufNext;
        for (int j = 15; j >= 0; j--) {
            unsigned int c = h[t * 16 + j];
            if (acc + c >= (unsigned)k) { g_T[b] = t * 16 + j; g_S[b] = (int)acc; break; }
            acc += c;
        }
    }
}

// ---------------------------------------------------------------------------
// Pass 3: compact. bin > T -> g_cand; bin == T -> g_binT + subhist[bits 8..20)
// grid (BPB, N) x HT
// ---------------------------------------------------------------------------
__device__ __forceinline__ void compact_one(unsigned int m, unsigned int off,
                                            int b, int T) {
    int bin = (int)(m >> 20);
    if (bin < T) return;
    unsigned long long key = ((unsigned long long)m << 32) |
                             (unsigned long long)(0xFFFFFFFFu - off);
    if (bin > T) {
        int p = atomicAdd(&g_count[b], 1);
        if (p < CAND_MAX) g_cand[b * CAND_MAX + p] = key;
    } else {
        atomicAdd(&g_subhist[b * NBINS + ((m >> 8) & 0xFFFu)], 1u);
        int p = atomicAdd(&g_btcount[b], 1);
        if (p < BT_MAX) g_binT[b * BT_MAX + p] = key;
    }
}

__global__ void compact_kernel(const float* __restrict__ scores, int A) {
    const int b = blockIdx.y;
    __shared__ int sT;
    if (threadIdx.x == 0) sT = g_T[b];
    __syncthreads();
    const int T = sT;
    const size_t base = (size_t)b * (size_t)A;

    if ((A & 3) == 0) {
        const float4* s4 = (const float4*)(scores + base);
        const int A4 = A >> 2;
        for (int i = blockIdx.x * HT + threadIdx.x; i < A4; i += BPB * HT) {
            float4 v = s4[i];
            unsigned int o = (unsigned int)(i << 2);
            compact_one(mono_f32(v.x), o + 0u, b, T);
            compact_one(mono_f32(v.y), o + 1u, b, T);
            compact_one(mono_f32(v.z), o + 2u, b, T);
            compact_one(mono_f32(v.w), o + 3u, b, T);
        }
    } else {
        for (int i = blockIdx.x * HT + threadIdx.x; i < A; i += BPB * HT)
            compact_one(mono_f32(scores[base + i]), (unsigned)i, b, T);
    }
}

// ---------------------------------------------------------------------------
// Pass 4: refine sub-threshold T2 within bin T; append qualifying bin-T keys
// to g_cand; publish g_total. grid N x 1024
// ---------------------------------------------------------------------------
__global__ void refine_kernel(int k) {
    __shared__ unsigned int sh[NBINS];
    __shared__ unsigned int tmp[1024];
    __shared__ int sT2;
    const int b = blockIdx.x;
    const int t = threadIdx.x;

    for (int i = t; i < NBINS; i += 1024) sh[i] = g_subhist[b * NBINS + i];
    const int k2 = k - g_S[b];   // >= 1 by construction
    __syncthreads();

    unsigned int seg = sh[t * 4] + sh[t * 4 + 1] + sh[t * 4 + 2] + sh[t * 4 + 3];
    tmp[t] = seg;
    __syncthreads();
    for (int d = 1; d < 1024; d <<= 1) {
        unsigned int v = (t + d < 1024) ? tmp[t + d] : 0u;
        __syncthreads();
        tmp[t] += v;
        __syncthreads();
    }
    unsigned int sufMine = tmp[t];
    unsigned int sufNext = (t + 1 < 1024) ? tmp[t + 1] : 0u;
    if (sufMine >= (unsigned)k2 && sufNext < (unsigned)k2) {
        unsigned int acc = sufNext;
        for (int j = 3; j >= 0; j--) {
            unsigned int c = sh[t * 4 + j];
            if (acc + c >= (unsigned)k2) { sT2 = t * 4 + j; break; }
            acc += c;
        }
    }
    __syncthreads();
    const int T2 = sT2;
    const int BT = min(g_btcount[b], BT_MAX);
    for (int i = t; i < BT; i += 1024) {
        unsigned long long key = g_binT[b * BT_MAX + i];
        if ((int)((key >> 40) & 0xFFFull) >= T2) {
            int p = atomicAdd(&g_count[b], 1);
            if (p < CAND_MAX) g_cand[b * CAND_MAX + p] = key;
        }
    }
    __syncthreads();
    if (t == 0) g_total[b] = min(g_count[b], CAND_MAX);
}

// ---------------------------------------------------------------------------
// Pass 5: rank counting. Each block owns a chunk of keys (smem broadcast);
// every thread counts how many chunk keys beat its candidates; atomicAdd
// partial ranks. grid (RB, N) x 1024
// ---------------------------------------------------------------------------
__global__ void __launch_bounds__(1024) rank_kernel() {
    __shared__ unsigned long long ck[(CAND_MAX + RB - 1) / RB];  // 128
    const int b = blockIdx.y;
    const int t = threadIdx.x;
    const int Ct = g_total[b];
    const int chunk = (Ct + RB - 1) / RB;
    const int begin = blockIdx.x * chunk;
    int len = Ct - begin;
    if (len > chunk) len = chunk;
    if (len < 0) len = 0;

    for (int j = t; j < len; j += 1024)
        ck[j] = g_cand[b * CAND_MAX + begin + j];
    __syncthreads();
    if (len == 0) return;

    // up to 4 candidates per thread (Ct <= 4096)
    unsigned long long m0 = 0, m1 = 0, m2 = 0, m3 = 0;
    const int i0 = t, i1 = t + 1024, i2 = t + 2048, i3 = t + 3072;
    const unsigned long long* cand = &g_cand[b * CAND_MAX];
    if (i0 < Ct) m0 = cand[i0];
    if (i1 < Ct) m1 = cand[i1];
    if (i2 < Ct) m2 = cand[i2];
    if (i3 < Ct) m3 = cand[i3];

    int c0 = 0, c1 = 0, c2 = 0, c3 = 0;
    for (int j = 0; j < len; j++) {
        unsigned long long kj = ck[j];
        c0 += (kj > m0);
        c1 += (kj > m1);
        c2 += (kj > m2);
        c3 += (kj > m3);
    }
    int* rank = &g_rank[b * CAND_MAX];
    if (i0 < Ct && c0) atomicAdd(&rank[i0], c0);
    if (i1 < Ct && c1) atomicAdd(&rank[i1], c1);
    if (i2 < Ct && c2) atomicAdd(&rank[i2], c2);
    if (i3 < Ct && c3) atomicAdd(&rank[i3], c3);
}

// ---------------------------------------------------------------------------
// Pass 6: decode + scatter by rank. grid (CAND_MAX/1024, N) x 1024
// ---------------------------------------------------------------------------
__global__ void decode_kernel(const float* __restrict__ anchors,
                              const float* __restrict__ breg,
                              float* __restrict__ out,
                              int A, int k) {
    const int b = blockIdx.y;
    const int i = blockIdx.x * 1024 + threadIdx.x;
    if (i >= g_total[b]) return;
    const int r = g_rank[b * CAND_MAX + i];
    if (r >= k) return;

    const unsigned long long key = g_cand[b * CAND_MAX + i];
    const float CLIP = 4.135166556742356f;   // log(1000/16)
    const size_t base = (size_t)b * (size_t)A;
    unsigned int idx = 0xFFFFFFFFu - (unsigned int)(key & 0xFFFFFFFFull);
    float sc = inv_mono((unsigned int)(key >> 32));
    size_t g4 = (base + (size_t)idx) * 4;

    float4 box = *(const float4*)(anchors + g4);
    float4 rc  = *(const float4*)(breg + g4);

    float w  = box.z - box.x + 1.0f;
    float h  = box.w - box.y + 1.0f;
    float cx = box.x + 0.5f * w;
    float cy = box.y + 0.5f * h;

    float dw = fminf(rc.z, CLIP);
    float dh = fminf(rc.w, CLIP);

    float pcx = rc.x * w + cx;
    float pcy = rc.y * h + cy;
    float pw  = expf(dw) * w;
    float ph  = expf(dh) * h;

    float* o = out + ((size_t)b * k + r) * 5;
    o[0] = pcx - 0.5f * pw;
    o[1] = pcy - 0.5f * ph;
    o[2] = pcx + 0.5f * pw - 1.0f;
    o[3] = pcy + 0.5f * ph - 1.0f;
    o[4] = sc;
}

// ---------------------------------------------------------------------------
extern "C" void kernel_launch(void* const* d_in, const int* in_sizes, int n_in,
                              void* d_out, int out_size) {
    const float* anchors    = (const float*)d_in[0];
    const float* objectness = (const float*)d_in[1];
    const float* breg       = (const float*)d_in[2];
    float* out = (float*)d_out;

    const int NA = in_sizes[1];
    const int k  = 2000;
    const int N  = out_size / (k * 5);
    const int A  = NA / N;

    void* hptr = nullptr;
    cudaGetSymbolAddress(&hptr, g_hist);
    cudaMemsetAsync(hptr, 0, sizeof(unsigned int) * (size_t)N * NBINS);

    dim3 grid(BPB, N);
    hist_kernel<<<grid, HT>>>(objectness, A);
    thresh_kernel<<<N, 256>>>(k);
    compact_kernel<<<grid, HT>>>(objectness, A);
    refine_kernel<<<N, 1024>>>(k);
    rank_kernel<<<dim3(RB, N), 1024>>>();
    decode_kernel<<<dim3(CAND_MAX / 1024, N), 1024>>>(anchors, breg, out, A, k);
}